// round 5
// baseline (speedup 1.0000x reference)
#include <cuda_runtime.h>
#include <cstddef>

#define BATCH 16
#define NPB   262144            // 512*512 elements per batch image
#define TAU_F 0.1f
#define SMOOTH_F 0.1f
#define TILE  256
#define NTILES (NPB / TILE)     // 1024
#define GRID_MAIN 296
#define PAD   20                // floats per smem row (16B-aligned, conflict-free LDS.128)

// Global accumulators (scratch; zeroed by zero_kernel each launch)
__device__ float g_cross[BATCH * BATCH];
__device__ float g_sq1[BATCH];
__device__ float g_sq2[BATCH];
__device__ float g_pos[BATCH];
__device__ float g_dice[3];    // sumP, sumG, sumPG

__global__ void zero_kernel() {
    int i = threadIdx.x;
    if (i < BATCH * BATCH) g_cross[i] = 0.0f;
    if (i < BATCH) { g_sq1[i] = 0.0f; g_sq2[i] = 0.0f; g_pos[i] = 0.0f; }
    if (i < 3) g_dice[i] = 0.0f;
}

__device__ __forceinline__ float sigf(float x) {
    return 1.0f / (1.0f + __expf(-x));
}

__global__ void __launch_bounds__(256, 2)
main_kernel(const float* __restrict__ pred, const float* __restrict__ gt,
            const float* __restrict__ in1,  const float* __restrict__ in2,
            const float* __restrict__ msk)
{
    __shared__ float s1_sh[TILE][PAD];
    __shared__ float s2_sh[TILE][PAD];

    const int tid  = threadIdx.x;
    const int lane = tid & 31;
    const int w    = tid >> 5;

    // Phase A mapping: fixed batch per thread
    const int b = tid >> 4;     // 0..15
    const int j = tid & 15;     // 0..15

    // Per-thread base pointers (batch offset + thread's float4 slot)
    const size_t boff = (size_t)b * NPB + (size_t)(4 * j);
    const float* p_in1  = in1  + boff;
    const float* p_in2  = in2  + boff;
    const float* p_msk  = msk  + boff;
    const float* p_pred = pred + boff;
    const float* p_gt   = gt   + boff;

    // Phase B mapping: 4 cross blocks (8x8), K split 64 ways
    const int blk  = w & 3;
    const int b1b  = (blk >> 1) * 8;
    const int b2b  = (blk & 1) * 8;
    const int tsrt = ((w >> 2) * 32) + lane;   // 0..63

    float c[8][8];
#pragma unroll
    for (int i = 0; i < 8; i++)
#pragma unroll
        for (int jj = 0; jj < 8; jj++) c[i][jj] = 0.0f;

    float sq1a = 0.0f, sq2a = 0.0f, posa = 0.0f;
    float dP = 0.0f, dG = 0.0f, dPG = 0.0f;

    for (int tile = blockIdx.x; tile < NTILES; tile += gridDim.x) {
        const size_t base = (size_t)tile * TILE;
        __syncthreads();   // protect smem from prior Phase B readers

        // ---------------- Phase A: load + sigmoid + pointwise accum + stage ----------------
#pragma unroll
        for (int s = 0; s < 4; s++) {
            const int t = s * 64 + 4 * j;                 // local tile index (float4 granule)
            const size_t gidx = base + (size_t)(s * 64);
            const float4 x1 = *(const float4*)(p_in1  + gidx);
            const float4 x2 = *(const float4*)(p_in2  + gidx);
            const float4 mm = *(const float4*)(p_msk  + gidx);
            const float4 pp = *(const float4*)(p_pred + gidx);
            const float4 gg = *(const float4*)(p_gt   + gidx);

            const float x1v[4] = {x1.x, x1.y, x1.z, x1.w};
            const float x2v[4] = {x2.x, x2.y, x2.z, x2.w};
            const float mv[4]  = {mm.x, mm.y, mm.z, mm.w};
            const float pv[4]  = {pp.x, pp.y, pp.z, pp.w};
            const float gv[4]  = {gg.x, gg.y, gg.z, gg.w};

#pragma unroll
            for (int k = 0; k < 4; k++) {
                const float s1 = sigf(x1v[k]);
                const float s2 = sigf(x2v[k]);
                s1_sh[t + k][b] = s1;
                s2_sh[t + k][b] = s2;
                const float d = mv[k] * (s1 - s2);
                posa += d * d;
                sq1a += s1 * s1;
                sq2a += s2 * s2;
                const float sp = sigf(pv[k]);
                dP  += sp;
                dG  += gv[k];
                dPG += sp * gv[k];
            }
        }
        __syncthreads();

        // ---------------- Phase B: 16x16 Gram accumulation (8x8 register blocks) ----------
#pragma unroll
        for (int tt = 0; tt < 4; tt++) {
            const int t = tsrt + tt * 64;
            const float4 a0 = *(const float4*)&s1_sh[t][b1b];
            const float4 a1 = *(const float4*)&s1_sh[t][b1b + 4];
            const float4 v0 = *(const float4*)&s2_sh[t][b2b];
            const float4 v1 = *(const float4*)&s2_sh[t][b2b + 4];
            const float av[8] = {a0.x, a0.y, a0.z, a0.w, a1.x, a1.y, a1.z, a1.w};
            const float bv[8] = {v0.x, v0.y, v0.z, v0.w, v1.x, v1.y, v1.z, v1.w};
#pragma unroll
            for (int i = 0; i < 8; i++)
#pragma unroll
                for (int jj = 0; jj < 8; jj++)
                    c[i][jj] += av[i] * bv[jj];
        }
    }

    // ---------------- Reductions (all shuffles full-warp, unconditional) ----------------
#pragma unroll
    for (int i = 0; i < 8; i++) {
#pragma unroll
        for (int jj = 0; jj < 8; jj++) {
            float v = c[i][jj];
            v += __shfl_xor_sync(0xffffffffu, v, 16);
            v += __shfl_xor_sync(0xffffffffu, v, 8);
            v += __shfl_xor_sync(0xffffffffu, v, 4);
            v += __shfl_xor_sync(0xffffffffu, v, 2);
            v += __shfl_xor_sync(0xffffffffu, v, 1);
            if (lane == 0) atomicAdd(&g_cross[(b1b + i) * BATCH + (b2b + jj)], v);
        }
    }

    // Per-batch sums: reduce within the 16-lane group sharing batch b
#pragma unroll
    for (int off = 8; off >= 1; off >>= 1) {
        posa += __shfl_xor_sync(0xffffffffu, posa, off);
        sq1a += __shfl_xor_sync(0xffffffffu, sq1a, off);
        sq2a += __shfl_xor_sync(0xffffffffu, sq2a, off);
    }
    if ((lane & 15) == 0) {
        atomicAdd(&g_pos[b], posa);
        atomicAdd(&g_sq1[b], sq1a);
        atomicAdd(&g_sq2[b], sq2a);
    }

    // Dice sums: full-warp reduce
#pragma unroll
    for (int off = 16; off >= 1; off >>= 1) {
        dP  += __shfl_xor_sync(0xffffffffu, dP,  off);
        dG  += __shfl_xor_sync(0xffffffffu, dG,  off);
        dPG += __shfl_xor_sync(0xffffffffu, dPG, off);
    }
    if (lane == 0) {
        atomicAdd(&g_dice[0], dP);
        atomicAdd(&g_dice[1], dG);
        atomicAdd(&g_dice[2], dPG);
    }
}

__global__ void finalize_kernel(float* __restrict__ out, int out_size) {
    __shared__ float s_simneg[BATCH];
    __shared__ float s_loss[BATCH];

    const int tid = threadIdx.x;       // 256 threads
    const int b1  = tid >> 4;
    const int b2  = tid & 15;
    const float invN = 1.0f / (float)NPB;

    const float mse = (g_sq1[b1] + g_sq2[b2] - 2.0f * g_cross[b1 * BATCH + b2]) * invN;
    float sim = expf(-mse / TAU_F);
    if (b1 == b2) sim = 0.0f;          // exclude diagonal
    // reduce over b2 within 16-lane group (all 256 threads execute: full-mask OK)
#pragma unroll
    for (int off = 8; off >= 1; off >>= 1)
        sim += __shfl_xor_sync(0xffffffffu, sim, off);
    if (b2 == 0) s_simneg[b1] = sim;
    __syncthreads();

    // Per-batch loss via smem (no sub-warp sync anywhere)
    if (tid < BATCH) {
        const float simpos = expf(-(g_pos[tid] * invN) / TAU_F);
        s_loss[tid] = -logf(simpos / (simpos + s_simneg[tid]));
    }
    __syncthreads();

    if (tid == 0) {
        float l = 0.0f;
#pragma unroll
        for (int i = 0; i < BATCH; i++) l += s_loss[i];
        const float contrast = l * (1.0f / (float)BATCH);
        const float dice = 1.0f - (2.0f * g_dice[2] + SMOOTH_F) /
                                  (g_dice[0] + g_dice[1] + SMOOTH_F);
        out[0] = dice + contrast;
        if (out_size > 1) out[1] = dice;
        if (out_size > 2) out[2] = 0.0f;
        if (out_size > 3) out[3] = contrast;
    }
}

extern "C" void kernel_launch(void* const* d_in, const int* in_sizes, int n_in,
                              void* d_out, int out_size) {
    const float* pred = (const float*)d_in[0];
    const float* gt   = (const float*)d_in[1];
    const float* in1  = (const float*)d_in[2];
    const float* in2  = (const float*)d_in[3];
    const float* msk  = (const float*)d_in[4];
    float* out = (float*)d_out;

    zero_kernel<<<1, 256>>>();
    main_kernel<<<GRID_MAIN, 256>>>(pred, gt, in1, in2, msk);
    finalize_kernel<<<1, 256>>>(out, out_size);
}

// round 6
// speedup vs baseline: 2.0867x; 2.0867x over previous
#include <cuda_runtime.h>
#include <cstddef>

#define BATCH 16
#define NPB   262144            // 512*512 elements per batch image
#define TAU_F 0.1f
#define SMOOTH_F 0.1f
#define TILE  128
#define NTILES (NPB / TILE)     // 2048
#define GRID_MAIN 296
#define ROWLEN 132              // floats per smem row (16B-aligned; stores/loads conflict-free)

// Global accumulators. Zero at module load; finalize_kernel re-zeroes after
// consuming them, so every kernel_launch invocation starts from zero state.
__device__ float g_cross[BATCH * BATCH];
__device__ float g_sq1[BATCH];
__device__ float g_sq2[BATCH];
__device__ float g_pos[BATCH];
__device__ float g_dice[3];    // sumP, sumG, sumPG

__device__ __forceinline__ float sigf(float x) {
    // sigmoid via ex2.approx + rcp.approx: ~4 ops, 2 MUFU. rel err ~2^-22.
    float e = __expf(-x);
    float r;
    asm("rcp.approx.f32 %0, %1;" : "=f"(r) : "f"(1.0f + e));
    return r;
}

__global__ void __launch_bounds__(256, 2)
main_kernel(const float* __restrict__ pred, const float* __restrict__ gt,
            const float* __restrict__ in1,  const float* __restrict__ in2,
            const float* __restrict__ msk)
{
    __shared__ float s1_sh[BATCH][ROWLEN];
    __shared__ float s2_sh[BATCH][ROWLEN];

    const int tid  = threadIdx.x;
    const int lane = tid & 31;
    const int w    = tid >> 5;

    // Phase A mapping: fixed batch per thread (16 lanes per batch, coalesced 256B runs)
    const int b = tid >> 4;     // 0..15
    const int j = tid & 15;     // 0..15

    const size_t boff = (size_t)b * NPB + (size_t)(4 * j);
    const float* p_in1  = in1  + boff;
    const float* p_in2  = in2  + boff;
    const float* p_msk  = msk  + boff;
    const float* p_pred = pred + boff;
    const float* p_gt   = gt   + boff;

    // Phase B mapping: warp w owns a disjoint 4x8 block of the 16x16 Gram,
    // accumulated over the FULL tile K (lanes split K 32-way, float4 granules).
    const int b1b = (w & 3) * 4;        // row block: 0,4,8,12
    const int b2b = (w >> 2) * 8;       // col block: 0 or 8
    const int tb  = lane * 4;           // 0..124, covers TILE=128 exactly

    float c[4][8];
#pragma unroll
    for (int i = 0; i < 4; i++)
#pragma unroll
        for (int jj = 0; jj < 8; jj++) c[i][jj] = 0.0f;

    float sq1a = 0.0f, sq2a = 0.0f, posa = 0.0f;
    float dP = 0.0f, dG = 0.0f, dPG = 0.0f;

    for (int tile = blockIdx.x; tile < NTILES; tile += GRID_MAIN) {
        const size_t base = (size_t)tile * TILE;
        __syncthreads();   // protect smem from prior Phase B readers

        // ---- Phase A: load + sigmoid + pointwise accum + stage (STS.128, conflict-free) ----
#pragma unroll
        for (int s = 0; s < 2; s++) {
            const int t = s * 64 + 4 * j;                 // local tile index (float4 granule)
            const size_t gidx = base + (size_t)(s * 64);
            const float4 x1 = *(const float4*)(p_in1  + gidx);
            const float4 x2 = *(const float4*)(p_in2  + gidx);
            const float4 mm = *(const float4*)(p_msk  + gidx);
            const float4 pp = *(const float4*)(p_pred + gidx);
            const float4 gg = *(const float4*)(p_gt   + gidx);

            float4 s1v, s2v;
            s1v.x = sigf(x1.x); s1v.y = sigf(x1.y); s1v.z = sigf(x1.z); s1v.w = sigf(x1.w);
            s2v.x = sigf(x2.x); s2v.y = sigf(x2.y); s2v.z = sigf(x2.z); s2v.w = sigf(x2.w);
            *(float4*)&s1_sh[b][t] = s1v;
            *(float4*)&s2_sh[b][t] = s2v;

            const float s1a[4] = {s1v.x, s1v.y, s1v.z, s1v.w};
            const float s2a[4] = {s2v.x, s2v.y, s2v.z, s2v.w};
            const float mv[4]  = {mm.x, mm.y, mm.z, mm.w};
            const float pv[4]  = {pp.x, pp.y, pp.z, pp.w};
            const float gv[4]  = {gg.x, gg.y, gg.z, gg.w};

#pragma unroll
            for (int k = 0; k < 4; k++) {
                const float d = mv[k] * (s1a[k] - s2a[k]);
                posa = fmaf(d, d, posa);
                sq1a = fmaf(s1a[k], s1a[k], sq1a);
                sq2a = fmaf(s2a[k], s2a[k], sq2a);
                const float sp = sigf(pv[k]);
                dP  += sp;
                dG  += gv[k];
                dPG = fmaf(sp, gv[k], dPG);
            }
        }
        __syncthreads();

        // ---- Phase B: 4x8 Gram block, float4 along K (LDS.128, conflict-free) ----
        float4 av[4], bv[8];
#pragma unroll
        for (int i = 0; i < 4; i++) av[i] = *(const float4*)&s1_sh[b1b + i][tb];
#pragma unroll
        for (int jj = 0; jj < 8; jj++) bv[jj] = *(const float4*)&s2_sh[b2b + jj][tb];
#pragma unroll
        for (int i = 0; i < 4; i++)
#pragma unroll
            for (int jj = 0; jj < 8; jj++) {
                c[i][jj] = fmaf(av[i].x, bv[jj].x, c[i][jj]);
                c[i][jj] = fmaf(av[i].y, bv[jj].y, c[i][jj]);
                c[i][jj] = fmaf(av[i].z, bv[jj].z, c[i][jj]);
                c[i][jj] = fmaf(av[i].w, bv[jj].w, c[i][jj]);
            }
    }

    // ---- Reductions (all shuffles full-warp, unconditional) ----
    // Each warp owns a disjoint 4x8 Gram block: butterfly then lane0 atomics (32/warp).
#pragma unroll
    for (int i = 0; i < 4; i++) {
#pragma unroll
        for (int jj = 0; jj < 8; jj++) {
            float v = c[i][jj];
            v += __shfl_xor_sync(0xffffffffu, v, 16);
            v += __shfl_xor_sync(0xffffffffu, v, 8);
            v += __shfl_xor_sync(0xffffffffu, v, 4);
            v += __shfl_xor_sync(0xffffffffu, v, 2);
            v += __shfl_xor_sync(0xffffffffu, v, 1);
            if (lane == 0) atomicAdd(&g_cross[(b1b + i) * BATCH + (b2b + jj)], v);
        }
    }

    // Per-batch sums: reduce within the 16-lane group sharing batch b
#pragma unroll
    for (int off = 8; off >= 1; off >>= 1) {
        posa += __shfl_xor_sync(0xffffffffu, posa, off);
        sq1a += __shfl_xor_sync(0xffffffffu, sq1a, off);
        sq2a += __shfl_xor_sync(0xffffffffu, sq2a, off);
    }
    if ((lane & 15) == 0) {
        atomicAdd(&g_pos[b], posa);
        atomicAdd(&g_sq1[b], sq1a);
        atomicAdd(&g_sq2[b], sq2a);
    }

    // Dice sums: full-warp reduce
#pragma unroll
    for (int off = 16; off >= 1; off >>= 1) {
        dP  += __shfl_xor_sync(0xffffffffu, dP,  off);
        dG  += __shfl_xor_sync(0xffffffffu, dG,  off);
        dPG += __shfl_xor_sync(0xffffffffu, dPG, off);
    }
    if (lane == 0) {
        atomicAdd(&g_dice[0], dP);
        atomicAdd(&g_dice[1], dG);
        atomicAdd(&g_dice[2], dPG);
    }
}

__global__ void finalize_kernel(float* __restrict__ out, int out_size) {
    __shared__ float s_simneg[BATCH];
    __shared__ float s_loss[BATCH];
    __shared__ float s_dice[3];

    const int tid = threadIdx.x;       // 256 threads
    const int b1  = tid >> 4;
    const int b2  = tid & 15;
    const float invN = 1.0f / (float)NPB;

    // Snapshot all accumulator state into registers/smem
    const float r_cross = g_cross[tid];
    const float r_sq1   = g_sq1[b1];
    const float r_sq2   = g_sq2[b2];
    const float r_pos   = (tid < BATCH) ? g_pos[tid] : 0.0f;
    if (tid < 3) s_dice[tid] = g_dice[tid];
    __syncthreads();

    // Re-zero accumulators for the next graph replay
    g_cross[tid] = 0.0f;
    if (tid < BATCH) { g_pos[tid] = 0.0f; g_sq1[tid] = 0.0f; g_sq2[tid] = 0.0f; }
    if (tid < 3) g_dice[tid] = 0.0f;

    const float mse = (r_sq1 + r_sq2 - 2.0f * r_cross) * invN;
    float sim = expf(-mse / TAU_F);
    if (b1 == b2) sim = 0.0f;          // exclude diagonal
    // reduce over b2 within 16-lane group (all 256 threads execute: full-mask OK)
#pragma unroll
    for (int off = 8; off >= 1; off >>= 1)
        sim += __shfl_xor_sync(0xffffffffu, sim, off);
    if (b2 == 0) s_simneg[b1] = sim;
    __syncthreads();

    if (tid < BATCH) {
        const float simpos = expf(-(r_pos * invN) / TAU_F);
        s_loss[tid] = -logf(simpos / (simpos + s_simneg[tid]));
    }
    __syncthreads();

    if (tid == 0) {
        float l = 0.0f;
#pragma unroll
        for (int i = 0; i < BATCH; i++) l += s_loss[i];
        const float contrast = l * (1.0f / (float)BATCH);
        const float dice = 1.0f - (2.0f * s_dice[2] + SMOOTH_F) /
                                  (s_dice[0] + s_dice[1] + SMOOTH_F);
        out[0] = dice + contrast;
        if (out_size > 1) out[1] = dice;
        if (out_size > 2) out[2] = 0.0f;
        if (out_size > 3) out[3] = contrast;
    }
}

extern "C" void kernel_launch(void* const* d_in, const int* in_sizes, int n_in,
                              void* d_out, int out_size) {
    const float* pred = (const float*)d_in[0];
    const float* gt   = (const float*)d_in[1];
    const float* in1  = (const float*)d_in[2];
    const float* in2  = (const float*)d_in[3];
    const float* msk  = (const float*)d_in[4];
    float* out = (float*)d_out;

    main_kernel<<<GRID_MAIN, 256>>>(pred, gt, in1, in2, msk);
    finalize_kernel<<<1, 256>>>(out, out_size);
}

// round 7
// speedup vs baseline: 2.0944x; 1.0037x over previous
#include <cuda_runtime.h>
#include <cstddef>

#define BATCH 16
#define NPB   262144            // 512*512 elements per batch image
#define TAU_F 0.1f
#define SMOOTH_F 0.1f
#define TILE  128
#define NTILES (NPB / TILE)     // 2048
#define GRID_MAIN 296
#define ROWLEN 132              // floats per smem row (16B-aligned; conflict-free)

// Global accumulators. Zero at module load; the fused finalize re-zeroes them
// after consuming, so every kernel_launch/graph replay starts from zero state.
__device__ float g_cross[BATCH * BATCH];
__device__ float g_sq1[BATCH];
__device__ float g_sq2[BATCH];
__device__ float g_pos[BATCH];
__device__ float g_dice[3];            // sumP, sumG, sumPG
__device__ unsigned int g_done;        // block-completion ticket

__device__ __forceinline__ float sigf(float x) {
    float e = __expf(-x);
    float r;
    asm("rcp.approx.f32 %0, %1;" : "=f"(r) : "f"(1.0f + e));
    return r;
}

// Packed fp32 FMA: d = a*b + d (two lanes at once). sm_100+ PTX.
__device__ __forceinline__ void fma2(unsigned long long& d,
                                     unsigned long long a,
                                     unsigned long long b) {
    asm("fma.rn.f32x2 %0, %1, %2, %0;" : "+l"(d) : "l"(a), "l"(b));
}

__device__ __forceinline__ float lo_f(unsigned long long v) {
    return __uint_as_float((unsigned int)(v & 0xffffffffu));
}
__device__ __forceinline__ float hi_f(unsigned long long v) {
    return __uint_as_float((unsigned int)(v >> 32));
}

__global__ void __launch_bounds__(256, 2)
main_kernel(const float* __restrict__ pred, const float* __restrict__ gt,
            const float* __restrict__ in1,  const float* __restrict__ in2,
            const float* __restrict__ msk,
            float* __restrict__ out, int out_size)
{
    __shared__ float s1_sh[BATCH][ROWLEN];
    __shared__ float s2_sh[BATCH][ROWLEN];
    __shared__ unsigned int s_islast;

    const int tid  = threadIdx.x;
    const int lane = tid & 31;
    const int w    = tid >> 5;

    // Phase A mapping: fixed batch per thread (16 lanes per batch)
    const int b = tid >> 4;     // 0..15
    const int j = tid & 15;     // 0..15

    const size_t boff = (size_t)b * NPB + (size_t)(4 * j);
    const float* p_in1  = in1  + boff;
    const float* p_in2  = in2  + boff;
    const float* p_msk  = msk  + boff;
    const float* p_pred = pred + boff;
    const float* p_gt   = gt   + boff;

    // Phase B mapping: warp w owns a disjoint 4x8 block of the 16x16 Gram.
    const int b1b = (w & 3) * 4;        // row block: 0,4,8,12
    const int b2b = (w >> 2) * 8;       // col block: 0 or 8
    const int tb  = lane * 4;           // float index into K, 16B granule

    // f32x2 accumulators: c2[i][jj] holds two partial sums (even/odd K pairs)
    unsigned long long c2[4][8];
#pragma unroll
    for (int i = 0; i < 4; i++)
#pragma unroll
        for (int jj = 0; jj < 8; jj++) c2[i][jj] = 0ull;

    float sq1a = 0.0f, sq2a = 0.0f, posa = 0.0f;
    float dP = 0.0f, dG = 0.0f, dPG = 0.0f;

    for (int tile = blockIdx.x; tile < NTILES; tile += GRID_MAIN) {
        const size_t base = (size_t)tile * TILE;
        __syncthreads();   // protect smem from prior Phase B readers

        // ---- Phase A: load + sigmoid + pointwise accum + stage ----
#pragma unroll
        for (int s = 0; s < 2; s++) {
            const int t = s * 64 + 4 * j;
            const size_t gidx = base + (size_t)(s * 64);
            const float4 x1 = *(const float4*)(p_in1  + gidx);
            const float4 x2 = *(const float4*)(p_in2  + gidx);
            const float4 mm = *(const float4*)(p_msk  + gidx);
            const float4 pp = *(const float4*)(p_pred + gidx);
            const float4 gg = *(const float4*)(p_gt   + gidx);

            float4 s1v, s2v;
            s1v.x = sigf(x1.x); s1v.y = sigf(x1.y); s1v.z = sigf(x1.z); s1v.w = sigf(x1.w);
            s2v.x = sigf(x2.x); s2v.y = sigf(x2.y); s2v.z = sigf(x2.z); s2v.w = sigf(x2.w);
            *(float4*)&s1_sh[b][t] = s1v;
            *(float4*)&s2_sh[b][t] = s2v;

            const float s1a[4] = {s1v.x, s1v.y, s1v.z, s1v.w};
            const float s2a[4] = {s2v.x, s2v.y, s2v.z, s2v.w};
            const float mv[4]  = {mm.x, mm.y, mm.z, mm.w};
            const float pv[4]  = {pp.x, pp.y, pp.z, pp.w};
            const float gv[4]  = {gg.x, gg.y, gg.z, gg.w};

#pragma unroll
            for (int k = 0; k < 4; k++) {
                const float d = mv[k] * (s1a[k] - s2a[k]);
                posa = fmaf(d, d, posa);
                sq1a = fmaf(s1a[k], s1a[k], sq1a);
                sq2a = fmaf(s2a[k], s2a[k], sq2a);
                const float sp = sigf(pv[k]);
                dP  += sp;
                dG  += gv[k];
                dPG = fmaf(sp, gv[k], dPG);
            }
        }
        __syncthreads();

        // ---- Phase B: 4x8 Gram block via packed f32x2 FMA ----
        ulonglong2 av[4];
#pragma unroll
        for (int i = 0; i < 4; i++)
            av[i] = *(const ulonglong2*)&s1_sh[b1b + i][tb];
#pragma unroll
        for (int jj = 0; jj < 8; jj++) {
            const ulonglong2 bv = *(const ulonglong2*)&s2_sh[b2b + jj][tb];
#pragma unroll
            for (int i = 0; i < 4; i++) {
                fma2(c2[i][jj], av[i].x, bv.x);
                fma2(c2[i][jj], av[i].y, bv.y);
            }
        }
    }

    // ---- Reductions (all shuffles full-warp, unconditional) ----
#pragma unroll
    for (int i = 0; i < 4; i++) {
#pragma unroll
        for (int jj = 0; jj < 8; jj++) {
            float v = lo_f(c2[i][jj]) + hi_f(c2[i][jj]);
            v += __shfl_xor_sync(0xffffffffu, v, 16);
            v += __shfl_xor_sync(0xffffffffu, v, 8);
            v += __shfl_xor_sync(0xffffffffu, v, 4);
            v += __shfl_xor_sync(0xffffffffu, v, 2);
            v += __shfl_xor_sync(0xffffffffu, v, 1);
            if (lane == 0) atomicAdd(&g_cross[(b1b + i) * BATCH + (b2b + jj)], v);
        }
    }

#pragma unroll
    for (int off = 8; off >= 1; off >>= 1) {
        posa += __shfl_xor_sync(0xffffffffu, posa, off);
        sq1a += __shfl_xor_sync(0xffffffffu, sq1a, off);
        sq2a += __shfl_xor_sync(0xffffffffu, sq2a, off);
    }
    if ((lane & 15) == 0) {
        atomicAdd(&g_pos[b], posa);
        atomicAdd(&g_sq1[b], sq1a);
        atomicAdd(&g_sq2[b], sq2a);
    }

#pragma unroll
    for (int off = 16; off >= 1; off >>= 1) {
        dP  += __shfl_xor_sync(0xffffffffu, dP,  off);
        dG  += __shfl_xor_sync(0xffffffffu, dG,  off);
        dPG += __shfl_xor_sync(0xffffffffu, dPG, off);
    }
    if (lane == 0) {
        atomicAdd(&g_dice[0], dP);
        atomicAdd(&g_dice[1], dG);
        atomicAdd(&g_dice[2], dPG);
    }

    // ---- Last-block fused finalize ----
    __threadfence();
    if (tid == 0)
        s_islast = (atomicAdd(&g_done, 1u) == (unsigned)(GRID_MAIN - 1));
    __syncthreads();
    if (!s_islast) return;

    {
        __shared__ float s_simneg[BATCH];
        __shared__ float s_loss[BATCH];
        __shared__ float s_dice[3];

        const int b1 = tid >> 4;
        const int b2 = tid & 15;
        const float invN = 1.0f / (float)NPB;

        // Snapshot accumulators (L1-bypass loads: values live in L2 via atomics)
        const float r_cross = __ldcg(&g_cross[tid]);
        const float r_sq1   = __ldcg(&g_sq1[b1]);
        const float r_sq2   = __ldcg(&g_sq2[b2]);
        const float r_pos   = (tid < BATCH) ? __ldcg(&g_pos[tid]) : 0.0f;
        if (tid < 3) s_dice[tid] = __ldcg(&g_dice[tid]);
        __syncthreads();

        // Re-zero state for the next graph replay
        g_cross[tid] = 0.0f;
        if (tid < BATCH) { g_pos[tid] = 0.0f; g_sq1[tid] = 0.0f; g_sq2[tid] = 0.0f; }
        if (tid < 3) g_dice[tid] = 0.0f;
        if (tid == 0) g_done = 0u;

        const float mse = (r_sq1 + r_sq2 - 2.0f * r_cross) * invN;
        float sim = expf(-mse / TAU_F);
        if (b1 == b2) sim = 0.0f;
#pragma unroll
        for (int off = 8; off >= 1; off >>= 1)
            sim += __shfl_xor_sync(0xffffffffu, sim, off);  // all 256 threads execute
        if (b2 == 0) s_simneg[b1] = sim;
        __syncthreads();

        if (tid < BATCH) {
            const float simpos = expf(-(r_pos * invN) / TAU_F);
            s_loss[tid] = -logf(simpos / (simpos + s_simneg[tid]));
        }
        __syncthreads();

        if (tid == 0) {
            float l = 0.0f;
#pragma unroll
            for (int i = 0; i < BATCH; i++) l += s_loss[i];
            const float contrast = l * (1.0f / (float)BATCH);
            const float dice = 1.0f - (2.0f * s_dice[2] + SMOOTH_F) /
                                      (s_dice[0] + s_dice[1] + SMOOTH_F);
            out[0] = dice + contrast;
            if (out_size > 1) out[1] = dice;
            if (out_size > 2) out[2] = 0.0f;
            if (out_size > 3) out[3] = contrast;
        }
    }
}

extern "C" void kernel_launch(void* const* d_in, const int* in_sizes, int n_in,
                              void* d_out, int out_size) {
    const float* pred = (const float*)d_in[0];
    const float* gt   = (const float*)d_in[1];
    const float* in1  = (const float*)d_in[2];
    const float* in2  = (const float*)d_in[3];
    const float* msk  = (const float*)d_in[4];
    float* out = (float*)d_out;

    main_kernel<<<GRID_MAIN, 256>>>(pred, gt, in1, in2, msk, out, out_size);
}